// round 9
// baseline (speedup 1.0000x reference)
#include <cuda_runtime.h>
#include <math.h>

// Problem constants (fixed by the reference setup_inputs)
#define Bb 2
#define Tt 12
#define Nn 4096
#define Kk 16
#define Hh 4
#define Cc 16
#define Vv 3

#define BTNH (Bb*Tt*Nn*Hh)                  // 393216
#define NEDGE ((size_t)Bb*Tt*Nn*Kk)         // 1572864 edges (x Hh lanes in float4)
#define U_SIZE ((size_t)Bb*Tt*Nn*Kk*Hh)     // 6291456
#define BRNH (Bb*(Tt-1)*Nn*Hh)              // 360448

#define SZ_FEATURES 6291456
#define SZ_MULTIQ   3072
#define SZ_MULTIM   1024
#define SZ_NEAREST  69632

#define FLT_MIN_NORMAL 1.17549435e-38f

__device__ __forceinline__ float ftz(float x) {
    return (fabsf(x) < FLT_MIN_NORMAL) ? 0.f : x;
}

// Scratch / analysis results (static device memory — no runtime allocation)
__device__ float g_buf[(size_t)BTNH * Cc];   // general fallback only
__device__ float deg_buf[BTNH];              // [bt][n][h], h = float4 lane
__device__ int   d_diag_flags[2];
__device__ float d_Mdiag[Hh * Cc];
__device__ float d_Qdiag[Vv * Hh * Cc];

// ---------------------------------------------------------------------------
// K0: analyze multiM / multiQ (diagonal => bit-exact fast path allowed)
// ---------------------------------------------------------------------------
__global__ void k0_analyze(const float* __restrict__ M,
                           const float* __restrict__ Q)
{
    __shared__ int okM, okQ;
    if (threadIdx.x == 0) { okM = 1; okQ = 1; }
    __syncthreads();

    for (int i = threadIdx.x; i < Hh * Cc * Cc; i += blockDim.x) {
        int r = (i / Cc) % Cc, c = i % Cc;
        float v = M[i];
        if (r != c && v != 0.f) atomicAnd(&okM, 0);
        if (r == c) d_Mdiag[(i / (Cc * Cc)) * Cc + r] = v;
    }
    for (int i = threadIdx.x; i < Vv * Hh * Cc * Cc; i += blockDim.x) {
        int r = (i / Cc) % Cc, c = i % Cc;
        float v = Q[i];
        if (r != c && v != 0.f) atomicAnd(&okQ, 0);
        if (r == c) d_Qdiag[(i / (Cc * Cc)) * Cc + r] = v;
    }
    __syncthreads();
    if (threadIdx.x == 0) { d_diag_flags[0] = okM; d_diag_flags[1] = okQ; }
}

// ---------------------------------------------------------------------------
// K1 (fallback only): g = multiM @ f. Early-out when multiM diagonal.
// ---------------------------------------------------------------------------
__global__ void k1_compute_g(const float* __restrict__ f,
                             const float* __restrict__ M)
{
    if (d_diag_flags[0]) return;

    __shared__ float sM[Hh * Cc * Cc];
    for (int i = threadIdx.x; i < Hh * Cc * Cc; i += blockDim.x) sM[i] = M[i];
    __syncthreads();

    int idx = blockIdx.x * blockDim.x + threadIdx.x;
    if (idx >= BTNH) return;
    int h = idx & (Hh - 1);

    const float* fv = f + (size_t)idx * Cc;
    float x[Cc];
#pragma unroll
    for (int c = 0; c < Cc; c += 4) {
        float4 t = *reinterpret_cast<const float4*>(fv + c);
        x[c] = t.x; x[c+1] = t.y; x[c+2] = t.z; x[c+3] = t.w;
    }
    const float* Mh = sM + h * Cc * Cc;
    float y[Cc];
#pragma unroll
    for (int i = 0; i < Cc; i++) {
        float s = 0.f;
#pragma unroll
        for (int j = 0; j < Cc; j++) s = __fadd_rn(s, __fmul_rn(Mh[i * Cc + j], x[j]));
        y[i] = s;
    }
    float* gv = g_buf + (size_t)idx * Cc;
#pragma unroll
    for (int c = 0; c < Cc; c += 4) {
        float4 t; t.x = y[c]; t.y = y[c+1]; t.z = y[c+2]; t.w = y[c+3];
        *reinterpret_cast<float4*>(gv + c) = t;
    }
}

// ---------------------------------------------------------------------------
// K2: one thread per edge (bt, n, k), vectorized over h.
//   w[h] = ftz(expf(-sum_c (mv[h,c]*(xi-xj))^2)), deg via 16-lane shfl tree.
// Unified path: diag -> src=f, mv=Mdiag; general -> src=g_buf, mv=1.0 (exact).
// Block = 256 threads = 16 nodes x 16 k. Node rows staged in smem.
// ---------------------------------------------------------------------------
__global__ void __launch_bounds__(256) k2_w_deg(
        const float* __restrict__ f,
        const int* __restrict__ nn,
        float* __restrict__ out_u)
{
    __shared__ float sm[Hh * Cc];            // mv
    __shared__ float sfi[16 * Hh * Cc];      // 16 node rows x 256B = 4KB

    int diag = d_diag_flags[0];
    const float* src = diag ? f : g_buf;

    for (int i = threadIdx.x; i < Hh * Cc; i += blockDim.x)
        sm[i] = diag ? d_Mdiag[i] : 1.0f;

    int t   = threadIdx.x;
    int blk = blockIdx.x;
    int bt  = blk >> 8;                      // blk / 256 (256 blocks per bt)
    int n0  = (blk & 255) << 4;              // 16 nodes per block
    int k   = t & 15;
    int nl  = t >> 4;
    int n   = n0 + nl;

    // stage the 16 source rows (coalesced: exactly 1 float4 per thread)
    {
        const float4* gsrc = reinterpret_cast<const float4*>(
            src + ((size_t)bt * Nn + n0) * Hh * Cc);
        reinterpret_cast<float4*>(sfi)[t] = gsrc[t];
    }
    __syncthreads();

    int j = nn[n * (Kk + 1) + 1 + k];

    float w0 = 0.f, w1 = 0.f, w2 = 0.f, w3 = 0.f;
    if (j >= 0) {
        const float* fj = src + ((size_t)bt * Nn + j) * Hh * Cc;
        const float* fi = sfi + nl * Hh * Cc;
        float s[Hh];
#pragma unroll
        for (int h = 0; h < Hh; h++) {
            float acc = 0.f;
#pragma unroll
            for (int c = 0; c < Cc; c += 4) {
                float4 a = *reinterpret_cast<const float4*>(fj + h * Cc + c);
                float b0 = fi[h * Cc + c],     m0 = sm[h * Cc + c];
                float b1 = fi[h * Cc + c + 1], m1 = sm[h * Cc + c + 1];
                float b2 = fi[h * Cc + c + 2], m2 = sm[h * Cc + c + 2];
                float b3 = fi[h * Cc + c + 3], m3 = sm[h * Cc + c + 3];
                float a0 = __fmul_rn(m0, __fsub_rn(b0, a.x));
                float a1 = __fmul_rn(m1, __fsub_rn(b1, a.y));
                float a2 = __fmul_rn(m2, __fsub_rn(b2, a.z));
                float a3 = __fmul_rn(m3, __fsub_rn(b3, a.w));
                acc = __fadd_rn(acc, __fmul_rn(a0, a0));
                acc = __fadd_rn(acc, __fmul_rn(a1, a1));
                acc = __fadd_rn(acc, __fmul_rn(a2, a2));
                acc = __fadd_rn(acc, __fmul_rn(a3, a3));
            }
            s[h] = acc;
        }
        w0 = ftz(expf(-s[0]));
        w1 = ftz(expf(-s[1]));
        w2 = ftz(expf(-s[2]));
        w3 = ftz(expf(-s[3]));
    }

    // coalesced w store: 16 consecutive k-threads cover 256 contiguous bytes
    {
        float4 w4; w4.x = w0; w4.y = w1; w4.z = w2; w4.w = w3;
        reinterpret_cast<float4*>(out_u)[((size_t)bt * Nn + n) * Kk + k] = w4;
    }

    // deg = sum over the 16 k-lanes (butterfly tree within each 16-lane group)
    float d0 = w0, d1 = w1, d2 = w2, d3 = w3;
#pragma unroll
    for (int off = 1; off < 16; off <<= 1) {
        d0 += __shfl_xor_sync(0xffffffffu, d0, off);
        d1 += __shfl_xor_sync(0xffffffffu, d1, off);
        d2 += __shfl_xor_sync(0xffffffffu, d2, off);
        d3 += __shfl_xor_sync(0xffffffffu, d3, off);
    }
    if (k == 0) {
        float4 dg; dg.x = d0; dg.y = d1; dg.z = d2; dg.w = d3;
        reinterpret_cast<float4*>(deg_buf)[(size_t)bt * Nn + n] = dg;
    }
}

// ---------------------------------------------------------------------------
// K3: one thread per edge (bt, n, k), float4 over h.
//   u = ftz(w * inv),  inv = (dm>0) ? 1/dm : 0,  dm = sqrtf(ftz(degi*degj))
// ---------------------------------------------------------------------------
__global__ void __launch_bounds__(256) k3_normalize(
        const int* __restrict__ nn,
        float* __restrict__ out_u)
{
    size_t idx = (size_t)blockIdx.x * blockDim.x + threadIdx.x;
    if (idx >= NEDGE) return;
    int k  = (int)(idx & 15);
    int n  = (int)((idx >> 4) & (Nn - 1));
    int bt = (int)(idx >> 16);

    const float4* degv = reinterpret_cast<const float4*>(deg_buf);
    float4 di = degv[(size_t)bt * Nn + n];

    int j  = nn[n * (Kk + 1) + 1 + k];
    int jj = j % Nn; if (jj < 0) jj += Nn;
    float4 dj = degv[(size_t)bt * Nn + jj];

    float4* uv = reinterpret_cast<float4*>(out_u) + ((size_t)bt * Nn + n) * Kk + k;
    float4 u = *uv;

    float P, dm;
    P = ftz(__fmul_rn(di.x, dj.x)); dm = sqrtf(P);
    u.x = ftz(__fmul_rn(u.x, (dm > 0.f) ? __fdiv_rn(1.f, dm) : 0.f));
    P = ftz(__fmul_rn(di.y, dj.y)); dm = sqrtf(P);
    u.y = ftz(__fmul_rn(u.y, (dm > 0.f) ? __fdiv_rn(1.f, dm) : 0.f));
    P = ftz(__fmul_rn(di.z, dj.z)); dm = sqrtf(P);
    u.z = ftz(__fmul_rn(u.z, (dm > 0.f) ? __fdiv_rn(1.f, dm) : 0.f));
    P = ftz(__fmul_rn(di.w, dj.w)); dm = sqrtf(P);
    u.w = ftz(__fmul_rn(u.w, (dm > 0.f) ? __fdiv_rn(1.f, dm) : 0.f));

    *uv = u;
}

// ---------------------------------------------------------------------------
// K4: temporal path, diag fast path (unchanged from R8 win)
// ---------------------------------------------------------------------------
__global__ void k4_temporal(const float* __restrict__ f,
                            const float* __restrict__ Q,
                            float* __restrict__ out_d)
{
    __shared__ float sQ[Vv * Hh * Cc * Cc];
    __shared__ float sQd[Vv * Hh * Cc];
    int diag = d_diag_flags[1];
    if (diag) {
        for (int i = threadIdx.x; i < Vv * Hh * Cc; i += blockDim.x) sQd[i] = d_Qdiag[i];
    } else {
        for (int i = threadIdx.x; i < Vv * Hh * Cc * Cc; i += blockDim.x) sQ[i] = Q[i];
    }
    __syncthreads();

    int idx = blockIdx.x * blockDim.x + threadIdx.x;
    if (idx >= BRNH) return;
    int h  = idx & (Hh - 1);
    int n  = (idx >> 2) & (Nn - 1);
    int br = idx >> 14;
    int r  = br % (Tt - 1);
    int b  = br / (Tt - 1);
    int tcur = r + 1;

    const float* fb = f + (size_t)b * Tt * Nn * Hh * Cc;
    const float* fc = fb + (((size_t)tcur * Nn + n) * Hh + h) * Cc;

    float xc[Cc];
#pragma unroll
    for (int c = 0; c < Cc; c += 4) {
        float4 t = *reinterpret_cast<const float4*>(fc + c);
        xc[c] = t.x; xc[c+1] = t.y; xc[c+2] = t.z; xc[c+3] = t.w;
    }

    float wd[Vv];
    float indeg = 0.f;
#pragma unroll
    for (int v = 0; v < Vv; v++) {
        float w = 0.f;
        if (v <= r) {
            int tp = r - v;
            const float* fp = fb + (((size_t)tp * Nn + n) * Hh + h) * Cc;
            float d[Cc];
#pragma unroll
            for (int c = 0; c < Cc; c += 4) {
                float4 t = *reinterpret_cast<const float4*>(fp + c);
                d[c]   = __fsub_rn(t.x, xc[c]);
                d[c+1] = __fsub_rn(t.y, xc[c+1]);
                d[c+2] = __fsub_rn(t.z, xc[c+2]);
                d[c+3] = __fsub_rn(t.w, xc[c+3]);
            }
            if (diag) {
                const float* qv = sQd + (v * Hh + h) * Cc;
#pragma unroll
                for (int i = 0; i < Cc; i++) {
                    float a = __fmul_rn(qv[i], d[i]);
                    float e = expf(-__fmul_rn(a, a));
                    w = __fadd_rn(w, e);
                }
            } else {
                const float* Qh = sQ + (v * Hh + h) * Cc * Cc;
#pragma unroll
                for (int i = 0; i < Cc; i++) {
                    float a = 0.f;
#pragma unroll
                    for (int jx = 0; jx < Cc; jx++)
                        a = __fadd_rn(a, __fmul_rn(Qh[i * Cc + jx], d[jx]));
                    float e = expf(-__fmul_rn(a, a));
                    w = __fadd_rn(w, e);
                }
            }
        }
        wd[v] = w;
        indeg = __fadd_rn(indeg, w);
    }
    float inv = (indeg > 0.f) ? __fdiv_rn(1.f, indeg) : 0.f;

    size_t obase = ((size_t)(b * (Tt - 1) + r)) * Vv * Nn * Hh + (size_t)n * Hh + h;
#pragma unroll
    for (int v = 0; v < Vv; v++)
        out_d[obase + (size_t)v * Nn * Hh] = __fmul_rn(wd[v], inv);
}

// ---------------------------------------------------------------------------
extern "C" void kernel_launch(void* const* d_in, const int* in_sizes, int n_in,
                              void* d_out, int out_size)
{
    const float* features = nullptr;
    const float* multiQ   = nullptr;
    const float* multiM   = nullptr;
    const int*   nearest  = nullptr;
    for (int i = 0; i < n_in; i++) {
        switch (in_sizes[i]) {
            case SZ_FEATURES: features = (const float*)d_in[i]; break;
            case SZ_MULTIQ:   multiQ   = (const float*)d_in[i]; break;
            case SZ_MULTIM:   multiM   = (const float*)d_in[i]; break;
            case SZ_NEAREST:  nearest  = (const int*)  d_in[i]; break;
            default: break;
        }
    }

    float* out_u = (float*)d_out;
    float* out_d = (float*)d_out + U_SIZE;

    k0_analyze<<<1, 1024>>>(multiM, multiQ);
    {
        int threads = 256, blocks = (BTNH + threads - 1) / threads;
        k1_compute_g<<<blocks, threads>>>(features, multiM);   // no-op when diag
    }
    {
        int blocks = (int)(NEDGE / 256);                       // 6144
        k2_w_deg<<<blocks, 256>>>(features, nearest, out_u);
    }
    {
        int blocks = (int)((NEDGE + 255) / 256);
        k3_normalize<<<blocks, 256>>>(nearest, out_u);
    }
    {
        int threads = 256, blocks = (BRNH + threads - 1) / threads;
        k4_temporal<<<blocks, threads>>>(features, multiQ, out_d);
    }
}

// round 12
// speedup vs baseline: 1.4454x; 1.4454x over previous
#include <cuda_runtime.h>
#include <math.h>

// Problem constants (fixed by the reference setup_inputs)
#define Bb 2
#define Tt 12
#define Nn 4096
#define Kk 16
#define Hh 4
#define Cc 16
#define Vv 3

#define BTNH (Bb*Tt*Nn*Hh)                  // 393216
#define NEDGE ((size_t)Bb*Tt*Nn*Kk)         // 1572864
#define U_SIZE ((size_t)Bb*Tt*Nn*Kk*Hh)     // 6291456
#define BRNH (Bb*(Tt-1)*Nn*Hh)              // 360448

#define SZ_FEATURES 6291456
#define SZ_MULTIQ   3072
#define SZ_MULTIM   1024
#define SZ_NEAREST  69632

#define FLT_MIN_NORMAL 1.17549435e-38f

__device__ __forceinline__ float ftz(float x) {
    return (fabsf(x) < FLT_MIN_NORMAL) ? 0.f : x;
}

// Scratch / analysis results (static device memory — no runtime allocation)
__device__ float g_buf[(size_t)BTNH * Cc];   // general fallback only
__device__ float deg_buf[BTNH];              // [bt][n][h]
__device__ int   d_diag_flags[2];
__device__ float d_Mdiag[Hh * Cc];
__device__ float d_Qdiag[Vv * Hh * Cc];

// ---------------------------------------------------------------------------
// K0: analyze multiM / multiQ (diagonal => bit-exact fast path allowed)
// ---------------------------------------------------------------------------
__global__ void k0_analyze(const float* __restrict__ M,
                           const float* __restrict__ Q)
{
    __shared__ int okM, okQ;
    if (threadIdx.x == 0) { okM = 1; okQ = 1; }
    __syncthreads();

    for (int i = threadIdx.x; i < Hh * Cc * Cc; i += blockDim.x) {
        int r = (i / Cc) % Cc, c = i % Cc;
        float v = M[i];
        if (r != c && v != 0.f) atomicAnd(&okM, 0);
        if (r == c) d_Mdiag[(i / (Cc * Cc)) * Cc + r] = v;
    }
    for (int i = threadIdx.x; i < Vv * Hh * Cc * Cc; i += blockDim.x) {
        int r = (i / Cc) % Cc, c = i % Cc;
        float v = Q[i];
        if (r != c && v != 0.f) atomicAnd(&okQ, 0);
        if (r == c) d_Qdiag[(i / (Cc * Cc)) * Cc + r] = v;
    }
    __syncthreads();
    if (threadIdx.x == 0) { d_diag_flags[0] = okM; d_diag_flags[1] = okQ; }
}

// ---------------------------------------------------------------------------
// K1 (fallback only): g = multiM @ f. Early-out when multiM diagonal.
// ---------------------------------------------------------------------------
__global__ void k1_compute_g(const float* __restrict__ f,
                             const float* __restrict__ M)
{
    if (d_diag_flags[0]) return;

    __shared__ float sM[Hh * Cc * Cc];
    for (int i = threadIdx.x; i < Hh * Cc * Cc; i += blockDim.x) sM[i] = M[i];
    __syncthreads();

    int idx = blockIdx.x * blockDim.x + threadIdx.x;
    if (idx >= BTNH) return;
    int h = idx & (Hh - 1);

    const float* fv = f + (size_t)idx * Cc;
    float x[Cc];
#pragma unroll
    for (int c = 0; c < Cc; c += 4) {
        float4 t = *reinterpret_cast<const float4*>(fv + c);
        x[c] = t.x; x[c+1] = t.y; x[c+2] = t.z; x[c+3] = t.w;
    }
    const float* Mh = sM + h * Cc * Cc;
    float y[Cc];
#pragma unroll
    for (int i = 0; i < Cc; i++) {
        float s = 0.f;
#pragma unroll
        for (int j = 0; j < Cc; j++) s = __fadd_rn(s, __fmul_rn(Mh[i * Cc + j], x[j]));
        y[i] = s;
    }
    float* gv = g_buf + (size_t)idx * Cc;
#pragma unroll
    for (int c = 0; c < Cc; c += 4) {
        float4 t; t.x = y[c]; t.y = y[c+1]; t.z = y[c+2]; t.w = y[c+3];
        *reinterpret_cast<float4*>(gv + c) = t;
    }
}

// ---------------------------------------------------------------------------
// K2 (R8 winning layout): one thread per (bt,n,h); 16-neighbor loop.
// Diagonal fast path reads f directly; fallback reads g_buf with mv=1 exact.
// ---------------------------------------------------------------------------
__global__ void k2_w_deg(const float* __restrict__ f,
                         const int* __restrict__ nn,
                         float* __restrict__ out_u)
{
    __shared__ float sm[Hh * Cc];
    int diag = d_diag_flags[0];
    for (int i = threadIdx.x; i < Hh * Cc; i += blockDim.x)
        sm[i] = diag ? d_Mdiag[i] : 1.0f;
    __syncthreads();

    int idx = blockIdx.x * blockDim.x + threadIdx.x;
    if (idx >= BTNH) return;
    int h  = idx & (Hh - 1);
    int n  = (idx >> 2) & (Nn - 1);
    int bt = idx >> 14;

    const float* src = diag ? f : g_buf;
    const int*   nrow  = nn + n * (Kk + 1) + 1;
    float* ubase = out_u + (((size_t)bt * Nn + n) * Kk) * Hh + h;

    const float* fvi = src + (size_t)idx * Cc;
    float fi[Cc], mv[Cc];
#pragma unroll
    for (int c = 0; c < Cc; c += 4) {
        float4 t = *reinterpret_cast<const float4*>(fvi + c);
        fi[c] = t.x; fi[c+1] = t.y; fi[c+2] = t.z; fi[c+3] = t.w;
    }
#pragma unroll
    for (int c = 0; c < Cc; c++) mv[c] = sm[h * Cc + c];

    const float* fbase = src + (size_t)bt * Nn * Hh * Cc;
    float deg = 0.f;
#pragma unroll 4
    for (int k = 0; k < Kk; k++) {
        int j = nrow[k];
        float w = 0.f;
        if (j >= 0) {
            const float* fj = fbase + ((size_t)j * Hh + h) * Cc;
            float s = 0.f;
#pragma unroll
            for (int c = 0; c < Cc; c += 4) {
                float4 t = *reinterpret_cast<const float4*>(fj + c);
                float a0 = __fmul_rn(mv[c],   __fsub_rn(fi[c],   t.x));
                float a1 = __fmul_rn(mv[c+1], __fsub_rn(fi[c+1], t.y));
                float a2 = __fmul_rn(mv[c+2], __fsub_rn(fi[c+2], t.z));
                float a3 = __fmul_rn(mv[c+3], __fsub_rn(fi[c+3], t.w));
                s = __fadd_rn(s, __fmul_rn(a0, a0));
                s = __fadd_rn(s, __fmul_rn(a1, a1));
                s = __fadd_rn(s, __fmul_rn(a2, a2));
                s = __fadd_rn(s, __fmul_rn(a3, a3));
            }
            w = ftz(expf(-s));
        }
        deg = __fadd_rn(deg, w);
        ubase[(size_t)k * Hh] = w;
    }
    deg_buf[idx] = deg;
}

// ---------------------------------------------------------------------------
// K3 (R9 winning layout): one thread per edge (bt,n,k), float4 over h.
// ---------------------------------------------------------------------------
__global__ void __launch_bounds__(256) k3_normalize(
        const int* __restrict__ nn,
        float* __restrict__ out_u)
{
    size_t idx = (size_t)blockIdx.x * blockDim.x + threadIdx.x;
    if (idx >= NEDGE) return;
    int k  = (int)(idx & 15);
    int n  = (int)((idx >> 4) & (Nn - 1));
    int bt = (int)(idx >> 16);

    const float4* degv = reinterpret_cast<const float4*>(deg_buf);
    float4 di = degv[(size_t)bt * Nn + n];

    int j  = nn[n * (Kk + 1) + 1 + k];
    int jj = j % Nn; if (jj < 0) jj += Nn;
    float4 dj = degv[(size_t)bt * Nn + jj];

    float4* uv = reinterpret_cast<float4*>(out_u) + ((size_t)bt * Nn + n) * Kk + k;
    float4 u = *uv;

    float P, dm;
    P = ftz(__fmul_rn(di.x, dj.x)); dm = sqrtf(P);
    u.x = ftz(__fmul_rn(u.x, (dm > 0.f) ? __fdiv_rn(1.f, dm) : 0.f));
    P = ftz(__fmul_rn(di.y, dj.y)); dm = sqrtf(P);
    u.y = ftz(__fmul_rn(u.y, (dm > 0.f) ? __fdiv_rn(1.f, dm) : 0.f));
    P = ftz(__fmul_rn(di.z, dj.z)); dm = sqrtf(P);
    u.z = ftz(__fmul_rn(u.z, (dm > 0.f) ? __fdiv_rn(1.f, dm) : 0.f));
    P = ftz(__fmul_rn(di.w, dj.w)); dm = sqrtf(P);
    u.w = ftz(__fmul_rn(u.w, (dm > 0.f) ? __fdiv_rn(1.f, dm) : 0.f));

    *uv = u;
}

// ---------------------------------------------------------------------------
// K4: temporal path, diag fast path (unchanged from R8 win)
// ---------------------------------------------------------------------------
__global__ void k4_temporal(const float* __restrict__ f,
                            const float* __restrict__ Q,
                            float* __restrict__ out_d)
{
    __shared__ float sQ[Vv * Hh * Cc * Cc];
    __shared__ float sQd[Vv * Hh * Cc];
    int diag = d_diag_flags[1];
    if (diag) {
        for (int i = threadIdx.x; i < Vv * Hh * Cc; i += blockDim.x) sQd[i] = d_Qdiag[i];
    } else {
        for (int i = threadIdx.x; i < Vv * Hh * Cc * Cc; i += blockDim.x) sQ[i] = Q[i];
    }
    __syncthreads();

    int idx = blockIdx.x * blockDim.x + threadIdx.x;
    if (idx >= BRNH) return;
    int h  = idx & (Hh - 1);
    int n  = (idx >> 2) & (Nn - 1);
    int br = idx >> 14;
    int r  = br % (Tt - 1);
    int b  = br / (Tt - 1);
    int tcur = r + 1;

    const float* fb = f + (size_t)b * Tt * Nn * Hh * Cc;
    const float* fc = fb + (((size_t)tcur * Nn + n) * Hh + h) * Cc;

    float xc[Cc];
#pragma unroll
    for (int c = 0; c < Cc; c += 4) {
        float4 t = *reinterpret_cast<const float4*>(fc + c);
        xc[c] = t.x; xc[c+1] = t.y; xc[c+2] = t.z; xc[c+3] = t.w;
    }

    float wd[Vv];
    float indeg = 0.f;
#pragma unroll
    for (int v = 0; v < Vv; v++) {
        float w = 0.f;
        if (v <= r) {
            int tp = r - v;
            const float* fp = fb + (((size_t)tp * Nn + n) * Hh + h) * Cc;
            float d[Cc];
#pragma unroll
            for (int c = 0; c < Cc; c += 4) {
                float4 t = *reinterpret_cast<const float4*>(fp + c);
                d[c]   = __fsub_rn(t.x, xc[c]);
                d[c+1] = __fsub_rn(t.y, xc[c+1]);
                d[c+2] = __fsub_rn(t.z, xc[c+2]);
                d[c+3] = __fsub_rn(t.w, xc[c+3]);
            }
            if (diag) {
                const float* qv = sQd + (v * Hh + h) * Cc;
#pragma unroll
                for (int i = 0; i < Cc; i++) {
                    float a = __fmul_rn(qv[i], d[i]);
                    float e = expf(-__fmul_rn(a, a));
                    w = __fadd_rn(w, e);
                }
            } else {
                const float* Qh = sQ + (v * Hh + h) * Cc * Cc;
#pragma unroll
                for (int i = 0; i < Cc; i++) {
                    float a = 0.f;
#pragma unroll
                    for (int jx = 0; jx < Cc; jx++)
                        a = __fadd_rn(a, __fmul_rn(Qh[i * Cc + jx], d[jx]));
                    float e = expf(-__fmul_rn(a, a));
                    w = __fadd_rn(w, e);
                }
            }
        }
        wd[v] = w;
        indeg = __fadd_rn(indeg, w);
    }
    float inv = (indeg > 0.f) ? __fdiv_rn(1.f, indeg) : 0.f;

    size_t obase = ((size_t)(b * (Tt - 1) + r)) * Vv * Nn * Hh + (size_t)n * Hh + h;
#pragma unroll
    for (int v = 0; v < Vv; v++)
        out_d[obase + (size_t)v * Nn * Hh] = __fmul_rn(wd[v], inv);
}

// ---------------------------------------------------------------------------
extern "C" void kernel_launch(void* const* d_in, const int* in_sizes, int n_in,
                              void* d_out, int out_size)
{
    const float* features = nullptr;
    const float* multiQ   = nullptr;
    const float* multiM   = nullptr;
    const int*   nearest  = nullptr;
    for (int i = 0; i < n_in; i++) {
        switch (in_sizes[i]) {
            case SZ_FEATURES: features = (const float*)d_in[i]; break;
            case SZ_MULTIQ:   multiQ   = (const float*)d_in[i]; break;
            case SZ_MULTIM:   multiM   = (const float*)d_in[i]; break;
            case SZ_NEAREST:  nearest  = (const int*)  d_in[i]; break;
            default: break;
        }
    }

    float* out_u = (float*)d_out;
    float* out_d = (float*)d_out + U_SIZE;

    k0_analyze<<<1, 1024>>>(multiM, multiQ);
    {
        int threads = 256, blocks = (BTNH + threads - 1) / threads;
        k1_compute_g<<<blocks, threads>>>(features, multiM);   // no-op when diag
    }
    {
        int threads = 256, blocks = (BTNH + threads - 1) / threads;
        k2_w_deg<<<blocks, threads>>>(features, nearest, out_u);
    }
    {
        int blocks = (int)((NEDGE + 255) / 256);
        k3_normalize<<<blocks, 256>>>(nearest, out_u);
    }
    {
        int threads = 256, blocks = (BRNH + threads - 1) / threads;
        k4_temporal<<<blocks, threads>>>(features, multiQ, out_d);
    }
}